// round 11
// baseline (speedup 1.0000x reference)
#include <cuda_runtime.h>
#include <cstdint>

#define Nn   10000
#define Ee   160000
#define Sdim 512
#define Vdim 128
#define Hh   8
#define HDim 64
#define Rr   32
#define PI_F 3.14159265358979f

// ---------------- scratch (static device memory; no allocation) ----------------
__device__ float g_qs[Nn * Sdim];
__device__ float g_ks[Nn * Sdim];
__device__ float g_vs[Nn * Sdim];
__device__ float g_qv[Nn * Vdim * 3];
__device__ float g_kv[Nn * Vdim * 3];
__device__ float g_vv[Nn * Vdim * 3];
__device__ float g_logits[Ee * Hh];
__device__ float g_accs[Nn * Sdim];
__device__ float g_accv[Nn * Vdim * 3];
__device__ float g_outs[Nn * Sdim];
__device__ int   g_cnt[Nn];
__device__ int   g_pos[Nn];
__device__ int   g_off[Nn + 1];
__device__ int   g_perm[Ee];
__device__ int   g_idx[2 * Ee];
__device__ int   g_is64;

// ---------------- edge-index dtype detection + normalization ----------------
__global__ void detect_dtype(const int* __restrict__ raw)
{
    int zeros = 0;
    for (int i = 0; i < 64; i++)
        if (raw[2 * i + 1] == 0) zeros++;
    g_is64 = (zeros >= 60) ? 1 : 0;
}

__global__ void convert_idx(const int* __restrict__ raw)
{
    int e = blockIdx.x * blockDim.x + threadIdx.x;
    if (e < 2 * Ee) {
        int v = g_is64 ? raw[2 * e] : raw[e];
        g_idx[e] = v;
    }
}

// ---------------- SGEMM: C[M,512] tile (128x128) = A @ B + bias ----------------
// Double-buffered, BK=16, 256 threads, 8x8 micro-tile.
__device__ __forceinline__ void sgemm128(const float* __restrict__ A,
                                         const float* __restrict__ B,
                                         const float* __restrict__ bias,
                                         float* __restrict__ C,
                                         int col0, int M)
{
    constexpr int K = 512, NC = 512, BK = 16, NT = K / BK;
    __shared__ float As[2][BK][128];
    __shared__ float Bs[2][BK][128];
    const int tid  = threadIdx.x;
    const int row0 = blockIdx.y * 128;
    const int tx = tid & 15;
    const int ty = tid >> 4;

    const int aRow = tid >> 1;
    const int aCol = (tid & 1) << 3;
    const int bRow = tid >> 4;
    const int bCol = (tid & 15) << 3;

    const bool aValid = (row0 + aRow) < M;
    const float* aPtr = &A[(size_t)(row0 + aRow) * K];
    const float* bPtr = &B[(size_t)bRow * NC + col0 + bCol];

    float acc[8][8];
#pragma unroll
    for (int i = 0; i < 8; i++)
#pragma unroll
        for (int j = 0; j < 8; j++) acc[i][j] = 0.f;

    // prologue: tile 0 -> buffer 0
    {
        float4 a0 = make_float4(0.f,0.f,0.f,0.f), a1 = a0;
        if (aValid) {
            a0 = *reinterpret_cast<const float4*>(&aPtr[aCol]);
            a1 = *reinterpret_cast<const float4*>(&aPtr[aCol + 4]);
        }
        float4 b0 = *reinterpret_cast<const float4*>(&bPtr[0]);
        float4 b1 = *reinterpret_cast<const float4*>(&bPtr[4]);
        As[0][aCol+0][aRow]=a0.x; As[0][aCol+1][aRow]=a0.y;
        As[0][aCol+2][aRow]=a0.z; As[0][aCol+3][aRow]=a0.w;
        As[0][aCol+4][aRow]=a1.x; As[0][aCol+5][aRow]=a1.y;
        As[0][aCol+6][aRow]=a1.z; As[0][aCol+7][aRow]=a1.w;
        *reinterpret_cast<float4*>(&Bs[0][bRow][bCol])   = b0;
        *reinterpret_cast<float4*>(&Bs[0][bRow][bCol+4]) = b1;
    }
    __syncthreads();

    int buf = 0;
#pragma unroll 1
    for (int kt = 0; kt < NT; kt++) {
        float4 a0, a1, b0, b1;
        const bool more = (kt + 1) < NT;
        if (more) {
            int k0 = (kt + 1) * BK;
            a0 = make_float4(0.f,0.f,0.f,0.f); a1 = a0;
            if (aValid) {
                a0 = *reinterpret_cast<const float4*>(&aPtr[k0 + aCol]);
                a1 = *reinterpret_cast<const float4*>(&aPtr[k0 + aCol + 4]);
            }
            b0 = *reinterpret_cast<const float4*>(&bPtr[(size_t)k0 * NC]);
            b1 = *reinterpret_cast<const float4*>(&bPtr[(size_t)k0 * NC + 4]);
        }
#pragma unroll
        for (int k = 0; k < BK; k++) {
            float ar[8], br[8];
#pragma unroll
            for (int i = 0; i < 8; i++) ar[i] = As[buf][k][ty * 8 + i];
#pragma unroll
            for (int j = 0; j < 8; j++) br[j] = Bs[buf][k][tx * 8 + j];
#pragma unroll
            for (int i = 0; i < 8; i++)
#pragma unroll
                for (int j = 0; j < 8; j++) acc[i][j] += ar[i] * br[j];
        }
        if (more) {
            int nb = buf ^ 1;
            As[nb][aCol+0][aRow]=a0.x; As[nb][aCol+1][aRow]=a0.y;
            As[nb][aCol+2][aRow]=a0.z; As[nb][aCol+3][aRow]=a0.w;
            As[nb][aCol+4][aRow]=a1.x; As[nb][aCol+5][aRow]=a1.y;
            As[nb][aCol+6][aRow]=a1.z; As[nb][aCol+7][aRow]=a1.w;
            *reinterpret_cast<float4*>(&Bs[nb][bRow][bCol])   = b0;
            *reinterpret_cast<float4*>(&Bs[nb][bRow][bCol+4]) = b1;
        }
        __syncthreads();
        buf ^= 1;
    }

#pragma unroll
    for (int i = 0; i < 8; i++) {
        int r = row0 + ty * 8 + i;
        if (r < M) {
#pragma unroll
            for (int j = 0; j < 8; j += 4) {
                int c = col0 + tx * 8 + j;
                float4 o;
                o.x = acc[i][j + 0] + bias[c + 0];
                o.y = acc[i][j + 1] + bias[c + 1];
                o.z = acc[i][j + 2] + bias[c + 2];
                o.w = acc[i][j + 3] + bias[c + 3];
                *reinterpret_cast<float4*>(&C[(size_t)r * NC + c]) = o;
            }
        }
    }
}

// Fused Q/K/V projection: blockIdx.x -> {matrix, column block}
__global__ __launch_bounds__(256) void qkv_sgemm(
    const float* __restrict__ A,
    const float* __restrict__ Wq, const float* __restrict__ Wk,
    const float* __restrict__ Wv,
    const float* __restrict__ bq, const float* __restrict__ bk,
    const float* __restrict__ bv)
{
    const int mat  = blockIdx.x >> 2;
    const int col0 = (blockIdx.x & 3) * 128;
    const float* B; const float* bias; float* C;
    if (mat == 0)      { B = Wq; bias = bq; C = g_qs; }
    else if (mat == 1) { B = Wk; bias = bk; C = g_ks; }
    else               { B = Wv; bias = bv; C = g_vs; }
    sgemm128(A, B, bias, C, col0, Nn);
}

__global__ __launch_bounds__(256) void outs_gemm(const float* __restrict__ W,
                                                 const float* __restrict__ bias)
{
    sgemm128(g_accs, W, bias, g_outs, blockIdx.x * 128, Nn);
}

// -------- vector GEMM: C[n,w,i] = sum_v A[n,v,i]*W[v,w] (+bias[w]) (+resid) ----
__device__ __forceinline__ void vgemm_body(const float* __restrict__ A,
                                           const float* __restrict__ W,
                                           const float* __restrict__ bias,
                                           const float* __restrict__ resid,
                                           float* __restrict__ C)
{
    __shared__ float Ws[32][64];
    __shared__ float Vs[16][96];
    const int tid = threadIdx.x;
    const int n0 = blockIdx.y * 16;
    const int w0 = blockIdx.x * 64;
    const int wi = tid & 31;
    const int ni = tid >> 5;

    float acc[2][2][3];
#pragma unroll
    for (int a = 0; a < 2; a++)
#pragma unroll
        for (int b = 0; b < 2; b++)
#pragma unroll
            for (int c = 0; c < 3; c++) acc[a][b][c] = 0.f;

    for (int k0 = 0; k0 < 128; k0 += 32) {
#pragma unroll
        for (int t = 0; t < 2; t++) {
            int idx = tid * 8 + t * 4;
            int r = idx >> 6;
            int c = idx & 63;
            *reinterpret_cast<float4*>(&Ws[r][c]) =
                *reinterpret_cast<const float4*>(&W[(size_t)(k0 + r) * 128 + w0 + c]);
        }
#pragma unroll
        for (int t = 0; t < 6; t++) {
            int idx = tid + t * 256;
            int nd = idx / 96;
            int off = idx - nd * 96;
            Vs[nd][off] = A[(size_t)(n0 + nd) * 384 + k0 * 3 + off];
        }
        __syncthreads();
#pragma unroll
        for (int k = 0; k < 32; k++) {
            float b0 = Ws[k][wi * 2 + 0];
            float b1 = Ws[k][wi * 2 + 1];
#pragma unroll
            for (int nn = 0; nn < 2; nn++) {
#pragma unroll
                for (int ii = 0; ii < 3; ii++) {
                    float a = Vs[ni * 2 + nn][k * 3 + ii];
                    acc[nn][0][ii] += a * b0;
                    acc[nn][1][ii] += a * b1;
                }
            }
        }
        __syncthreads();
    }
#pragma unroll
    for (int nn = 0; nn < 2; nn++) {
        int n = n0 + ni * 2 + nn;
#pragma unroll
        for (int ww = 0; ww < 2; ww++) {
            int w = w0 + wi * 2 + ww;
            float bvv = bias ? bias[w] : 0.f;
#pragma unroll
            for (int ii = 0; ii < 3; ii++) {
                size_t o = (size_t)n * 384 + (size_t)w * 3 + ii;
                float v = acc[nn][ww][ii] + bvv;
                if (resid) v += resid[o];
                C[o] = v;
            }
        }
    }
}

__global__ void vqkv_gemm(const float* __restrict__ vecs,
                          const float* __restrict__ Wq, const float* __restrict__ Wk,
                          const float* __restrict__ Wv)
{
    const float* W; float* C;
    if (blockIdx.z == 0)      { W = Wq; C = g_qv; }
    else if (blockIdx.z == 1) { W = Wk; C = g_kv; }
    else                      { W = Wv; C = g_vv; }
    vgemm_body(vecs, W, nullptr, nullptr, C);
}

__global__ void vout_gemm(const float* __restrict__ W, const float* __restrict__ bias,
                          const float* __restrict__ vecs, float* __restrict__ out)
{
    vgemm_body(g_accv, W, bias, vecs, out);
}

// ---------------- CSR build ----------------
__global__ void zero_csr()
{
    int i = blockIdx.x * blockDim.x + threadIdx.x;
    if (i < Nn) { g_cnt[i] = 0; g_pos[i] = 0; }
}

__global__ void count_rows()
{
    int e = blockIdx.x * blockDim.x + threadIdx.x;
    if (e < Ee) atomicAdd(&g_cnt[g_idx[e]], 1);
}

__global__ void scan_kernel()
{
    __shared__ int warp_tot[32];
    __shared__ int carry_s;
    const int tid = threadIdx.x;
    const int lane = tid & 31, w = tid >> 5;
    if (tid == 0) { carry_s = 0; g_off[0] = 0; }
    __syncthreads();
    for (int base = 0; base < Nn; base += 1024) {
        int v = (base + tid < Nn) ? g_cnt[base + tid] : 0;
        int x = v;
#pragma unroll
        for (int o = 1; o < 32; o <<= 1) {
            int y = __shfl_up_sync(0xffffffffu, x, o);
            if (lane >= o) x += y;
        }
        if (lane == 31) warp_tot[w] = x;
        __syncthreads();
        if (w == 0) {
            int t = warp_tot[lane];
            int inc = t;
#pragma unroll
            for (int o = 1; o < 32; o <<= 1) {
                int y = __shfl_up_sync(0xffffffffu, inc, o);
                if (lane >= o) inc += y;
            }
            warp_tot[lane] = inc - t;
        }
        __syncthreads();
        int incl = x + warp_tot[w] + carry_s;
        if (base + tid < Nn) g_off[base + tid + 1] = incl;
        __syncthreads();
        if (tid == 1023) carry_s = incl;
        __syncthreads();
    }
}

__global__ void scatter_kernel()
{
    int e = blockIdx.x * blockDim.x + threadIdx.x;
    if (e < Ee) {
        int r = g_idx[e];
        int p = atomicAdd(&g_pos[r], 1);
        g_perm[g_off[r] + p] = e;
    }
}

// ---------------- per-edge logits: one warp per edge, CSR order ----------------
// Processing edges in g_perm order groups same-row edges onto consecutive warps,
// making the q-side rows L1-resident (halves L2 traffic vs random order).
__global__ __launch_bounds__(256) void edge_logits(
    const float* __restrict__ edge_vec,
    const float* __restrict__ W_edge,
    const float* __restrict__ b_edge)
{
    const int gwarp = (blockIdx.x * 256 + threadIdx.x) >> 5;
    const int lane  = threadIdx.x & 31;
    const int wid   = threadIdx.x >> 5;
    if (gwarp >= Ee) return;
    const int e   = g_perm[gwarp];      // CSR-sorted edge id
    const int row = g_idx[e];
    const int col = g_idx[Ee + e];

    __shared__ float sh_s[8][8];

    const float4* qp = reinterpret_cast<const float4*>(&g_qs[(size_t)row * Sdim]);
    const float4* kp = reinterpret_cast<const float4*>(&g_ks[(size_t)col * Sdim]);
    float hacc[4];
#pragma unroll
    for (int w = 0; w < 4; w++) {
        float4 q = qp[lane + 32 * w];
        float4 k = kp[lane + 32 * w];
        hacc[w] = q.x * k.x + q.y * k.y + q.z * k.z + q.w * k.w;
    }
    const float4* qv = reinterpret_cast<const float4*>(&g_qv[(size_t)row * 384]);
    const float4* kv = reinterpret_cast<const float4*>(&g_kv[(size_t)col * 384]);
    float pv = 0.f;
#pragma unroll
    for (int w = 0; w < 3; w++) {
        float4 q = qv[lane + 32 * w];
        float4 k = kv[lane + 32 * w];
        pv += q.x * k.x + q.y * k.y + q.z * k.z + q.w * k.w;
    }
#pragma unroll
    for (int o = 16; o; o >>= 1) pv += __shfl_xor_sync(0xffffffffu, pv, o);

#pragma unroll
    for (int w = 0; w < 4; w++)
#pragma unroll
        for (int o = 8; o; o >>= 1)
            hacc[w] += __shfl_down_sync(0xffffffffu, hacc[w], o);
    if (lane == 0) {
#pragma unroll
        for (int w = 0; w < 4; w++) sh_s[wid][2 * w] = hacc[w];
    }
    if (lane == 16) {
#pragma unroll
        for (int w = 0; w < 4; w++) sh_s[wid][2 * w + 1] = hacc[w];
    }

    float ex = edge_vec[(size_t)e * 3 + 0];
    float ey = edge_vec[(size_t)e * 3 + 1];
    float ez = edge_vec[(size_t)e * 3 + 2];
    float d  = sqrtf(ex * ex + ey * ey + ez * ez);
    float cut = (d < 10.f) ? 0.5f * (cosf(PI_F * d * 0.1f) + 1.f) : 0.f;
    float cs = cut / fmaxf(d, 1e-8f);
    float sr = sinf((float)(lane + 1) * (PI_F * 0.1f) * d) * cs;

    float t[8];
    const float* wr = &W_edge[lane * Hh];
#pragma unroll
    for (int h = 0; h < 8; h++) t[h] = sr * wr[h];
#pragma unroll
    for (int o = 16; o; o >>= 1)
#pragma unroll
        for (int h = 0; h < 8; h++)
            t[h] += __shfl_xor_sync(0xffffffffu, t[h], o);

    __syncwarp();
    if (lane == 0) {
        float av = pv * 0.5773502691896258f;
#pragma unroll
        for (int h = 0; h < 8; h++) {
            float logit = (sh_s[wid][h] + av + t[h] + b_edge[h]) * 0.125f;
            g_logits[(size_t)e * 8 + h] = logit;
        }
    }
}

// ---------------- per-node softmax + aggregation ----------------
__global__ void node_aggregate()
{
    const int n = blockIdx.x;
    const int tid = threadIdx.x;   // 512
    const int beg = g_off[n], end = g_off[n + 1];
    const int deg = end - beg;

    __shared__ unsigned m_u[8];
    __shared__ float m[8], ssum[8];
    constexpr int CH = 128;
    __shared__ float sh_attn[CH][8];
    __shared__ float sh_av[CH];
    __shared__ int   sh_col[CH];

    float acc_s = 0.f;
    float acc_v = 0.f;

    if (deg > 0) {
        if (tid < 8) { m_u[tid] = 0u; ssum[tid] = 0.f; }
        __syncthreads();
        for (int j = tid; j < deg; j += 512) {
            int e = g_perm[beg + j];
            const float* lp = &g_logits[(size_t)e * 8];
#pragma unroll
            for (int h = 0; h < 8; h++) {
                unsigned u = __float_as_uint(lp[h]);
                u = (u & 0x80000000u) ? ~u : (u | 0x80000000u);
                atomicMax(&m_u[h], u);
            }
        }
        __syncthreads();
        if (tid < 8) {
            unsigned u = m_u[tid];
            u = (u & 0x80000000u) ? (u & 0x7fffffffu) : ~u;
            m[tid] = __uint_as_float(u);
        }
        __syncthreads();
        for (int j = tid; j < deg; j += 512) {
            int e = g_perm[beg + j];
            const float* lp = &g_logits[(size_t)e * 8];
#pragma unroll
            for (int h = 0; h < 8; h++)
                atomicAdd(&ssum[h], expf(lp[h] - m[h]));
        }
        __syncthreads();

        const int h_own = tid >> 6;
        for (int c0 = 0; c0 < deg; c0 += CH) {
            int cn = min(CH, deg - c0);
            for (int j = tid; j < cn; j += 512) {
                int e = g_perm[beg + c0 + j];
                sh_col[j] = g_idx[Ee + e];
                const float* lp = &g_logits[(size_t)e * 8];
                float asum = 0.f;
#pragma unroll
                for (int h = 0; h < 8; h++) {
                    float a = expf(lp[h] - m[h]) / (ssum[h] + 1e-9f);
                    sh_attn[j][h] = a;
                    asum += a;
                }
                sh_av[j] = asum * 0.125f;
            }
            __syncthreads();
            for (int j = 0; j < cn; j++) {
                int col = sh_col[j];
                acc_s += sh_attn[j][h_own] * g_vs[(size_t)col * 512 + tid];
                if (tid < 384) acc_v += sh_av[j] * g_vv[(size_t)col * 384 + tid];
            }
            __syncthreads();
        }
    }
    g_accs[(size_t)n * 512 + tid] = acc_s;
    if (tid < 384) g_accv[(size_t)n * 384 + tid] = acc_v;
}

// ---------------- residual + layernorm ----------------
__global__ void ln_kernel(const float* __restrict__ scalars,
                          const float* __restrict__ gg, const float* __restrict__ bb,
                          float* __restrict__ out)
{
    const int n = blockIdx.x;
    const int tid = threadIdx.x;  // 512
    float x = scalars[(size_t)n * 512 + tid] + g_outs[(size_t)n * 512 + tid];

    __shared__ float red[16];
    __shared__ float s_mu, s_var;

    float s = x;
#pragma unroll
    for (int o = 16; o; o >>= 1) s += __shfl_down_sync(0xffffffffu, s, o);
    if ((tid & 31) == 0) red[tid >> 5] = s;
    __syncthreads();
    if (tid == 0) {
        float t = 0.f;
#pragma unroll
        for (int i = 0; i < 16; i++) t += red[i];
        s_mu = t * (1.f / 512.f);
    }
    __syncthreads();
    float d = x - s_mu;
    float v = d * d;
#pragma unroll
    for (int o = 16; o; o >>= 1) v += __shfl_down_sync(0xffffffffu, v, o);
    if ((tid & 31) == 0) red[tid >> 5] = v;
    __syncthreads();
    if (tid == 0) {
        float t = 0.f;
#pragma unroll
        for (int i = 0; i < 16; i++) t += red[i];
        s_var = t * (1.f / 512.f);
    }
    __syncthreads();
    out[(size_t)n * 512 + tid] = d * rsqrtf(s_var + 1e-5f) * gg[tid] + bb[tid];
}

// ---------------- launch ----------------
extern "C" void kernel_launch(void* const* d_in, const int* in_sizes, int n_in,
                              void* d_out, int out_size)
{
    const float* scalars  = (const float*)d_in[0];
    const float* vectors  = (const float*)d_in[1];
    const float* edge_vec = (const float*)d_in[2];
    const float* Wq_s = (const float*)d_in[3];
    const float* bq_s = (const float*)d_in[4];
    const float* Wk_s = (const float*)d_in[5];
    const float* bk_s = (const float*)d_in[6];
    const float* Wv_s = (const float*)d_in[7];
    const float* bv_s = (const float*)d_in[8];
    const float* Wq_v = (const float*)d_in[9];
    const float* Wk_v = (const float*)d_in[10];
    const float* Wv_v = (const float*)d_in[11];
    const float* Wout_s = (const float*)d_in[12];
    const float* bout_s = (const float*)d_in[13];
    const float* Wout_v = (const float*)d_in[14];
    const float* bout_v = (const float*)d_in[15];
    const float* W_edge = (const float*)d_in[16];
    const float* b_edge = (const float*)d_in[17];
    const float* ln_g   = (const float*)d_in[18];
    const float* ln_b   = (const float*)d_in[19];
    const int*   eidx_raw = (const int*)d_in[20];

    float* out_s = (float*)d_out;
    float* out_v = (float*)d_out + (size_t)Nn * Sdim;

    // normalize edge indices
    detect_dtype<<<1, 1>>>(eidx_raw);
    convert_idx<<<(2 * Ee + 255) / 256, 256>>>(eidx_raw);

    // CSR build
    zero_csr<<<(Nn + 255) / 256, 256>>>();
    count_rows<<<(Ee + 255) / 256, 256>>>();
    scan_kernel<<<1, 1024>>>();
    scatter_kernel<<<(Ee + 255) / 256, 256>>>();

    // projections
    qkv_sgemm<<<dim3(12, (Nn + 127) / 128), 256>>>(
        scalars, Wq_s, Wk_s, Wv_s, bq_s, bk_s, bv_s);
    vqkv_gemm<<<dim3(Vdim / 64, Nn / 16, 3), 256>>>(vectors, Wq_v, Wk_v, Wv_v);

    // attention
    edge_logits<<<(Ee * 32 + 255) / 256, 256>>>(edge_vec, W_edge, b_edge);
    node_aggregate<<<Nn, 512>>>();

    // outputs
    outs_gemm<<<dim3(4, (Nn + 127) / 128), 256>>>(Wout_s, bout_s);
    vout_gemm<<<dim3(Vdim / 64, Nn / 16), 256>>>(Wout_v, bout_v, vectors, out_v);
    ln_kernel<<<Nn, 512>>>(scalars, ln_g, ln_b, out_s);
}

// round 12
// speedup vs baseline: 1.1045x; 1.1045x over previous
#include <cuda_runtime.h>
#include <cstdint>

#define Nn   10000
#define Ee   160000
#define Sdim 512
#define Vdim 128
#define Hh   8
#define HDim 64
#define Rr   32
#define PI_F 3.14159265358979f

// ---------------- scratch (static device memory; no allocation) ----------------
__device__ float g_qs[Nn * Sdim];
__device__ float g_ks[Nn * Sdim];
__device__ float g_vs[Nn * Sdim];
__device__ float g_qv[Nn * Vdim * 3];
__device__ float g_kv[Nn * Vdim * 3];
__device__ float g_vv[Nn * Vdim * 3];
__device__ float g_logits[Ee * Hh];
__device__ float g_accs[Nn * Sdim];
__device__ float g_accv[Nn * Vdim * 3];
__device__ float g_outs[Nn * Sdim];
__device__ int   g_cnt[Nn];
__device__ int   g_pos[Nn];
__device__ int   g_off[Nn + 1];
__device__ int   g_perm[Ee];
__device__ int   g_idx[2 * Ee];
__device__ int   g_is64;

// ---------------- edge-index dtype detection + normalization ----------------
__global__ void detect_dtype(const int* __restrict__ raw)
{
    int zeros = 0;
    for (int i = 0; i < 64; i++)
        if (raw[2 * i + 1] == 0) zeros++;
    g_is64 = (zeros >= 60) ? 1 : 0;
}

__global__ void convert_idx(const int* __restrict__ raw)
{
    int e = blockIdx.x * blockDim.x + threadIdx.x;
    if (e < 2 * Ee) {
        int v = g_is64 ? raw[2 * e] : raw[e];
        g_idx[e] = v;
    }
}

// ---------------- SGEMM: C[M,512] tile (128x128) = A @ B + bias ----------------
// Double-buffered, BK=16, 256 threads, 8x8 micro-tile.
// Fragment mapping uses stride-16 rows/cols -> conflict-free LDS:
//   thread (tx,ty) owns rows {ty+16i} and cols {tx+16j}.
__device__ __forceinline__ void sgemm128(const float* __restrict__ A,
                                         const float* __restrict__ B,
                                         const float* __restrict__ bias,
                                         float* __restrict__ C,
                                         int col0, int M)
{
    constexpr int K = 512, NC = 512, BK = 16, NT = K / BK;
    __shared__ float As[2][BK][128];
    __shared__ float Bs[2][BK][128];
    const int tid  = threadIdx.x;
    const int row0 = blockIdx.y * 128;
    const int tx = tid & 15;
    const int ty = tid >> 4;

    const int aRow = tid >> 1;
    const int aCol = (tid & 1) << 3;
    const int bRow = tid >> 4;
    const int bCol = (tid & 15) << 3;

    const bool aValid = (row0 + aRow) < M;
    const float* aPtr = &A[(size_t)(row0 + aRow) * K];
    const float* bPtr = &B[(size_t)bRow * NC + col0 + bCol];

    float acc[8][8];
#pragma unroll
    for (int i = 0; i < 8; i++)
#pragma unroll
        for (int j = 0; j < 8; j++) acc[i][j] = 0.f;

    // prologue: tile 0 -> buffer 0
    {
        float4 a0 = make_float4(0.f,0.f,0.f,0.f), a1 = a0;
        if (aValid) {
            a0 = *reinterpret_cast<const float4*>(&aPtr[aCol]);
            a1 = *reinterpret_cast<const float4*>(&aPtr[aCol + 4]);
        }
        float4 b0 = *reinterpret_cast<const float4*>(&bPtr[0]);
        float4 b1 = *reinterpret_cast<const float4*>(&bPtr[4]);
        As[0][aCol+0][aRow]=a0.x; As[0][aCol+1][aRow]=a0.y;
        As[0][aCol+2][aRow]=a0.z; As[0][aCol+3][aRow]=a0.w;
        As[0][aCol+4][aRow]=a1.x; As[0][aCol+5][aRow]=a1.y;
        As[0][aCol+6][aRow]=a1.z; As[0][aCol+7][aRow]=a1.w;
        *reinterpret_cast<float4*>(&Bs[0][bRow][bCol])   = b0;
        *reinterpret_cast<float4*>(&Bs[0][bRow][bCol+4]) = b1;
    }
    __syncthreads();

    int buf = 0;
#pragma unroll 1
    for (int kt = 0; kt < NT; kt++) {
        float4 a0, a1, b0, b1;
        const bool more = (kt + 1) < NT;
        if (more) {
            int k0 = (kt + 1) * BK;
            a0 = make_float4(0.f,0.f,0.f,0.f); a1 = a0;
            if (aValid) {
                a0 = *reinterpret_cast<const float4*>(&aPtr[k0 + aCol]);
                a1 = *reinterpret_cast<const float4*>(&aPtr[k0 + aCol + 4]);
            }
            b0 = *reinterpret_cast<const float4*>(&bPtr[(size_t)k0 * NC]);
            b1 = *reinterpret_cast<const float4*>(&bPtr[(size_t)k0 * NC + 4]);
        }
#pragma unroll
        for (int k = 0; k < BK; k++) {
            float ar[8], br[8];
#pragma unroll
            for (int i = 0; i < 8; i++) ar[i] = As[buf][k][ty + 16 * i];
#pragma unroll
            for (int j = 0; j < 8; j++) br[j] = Bs[buf][k][tx + 16 * j];
#pragma unroll
            for (int i = 0; i < 8; i++)
#pragma unroll
                for (int j = 0; j < 8; j++) acc[i][j] += ar[i] * br[j];
        }
        if (more) {
            int nb = buf ^ 1;
            As[nb][aCol+0][aRow]=a0.x; As[nb][aCol+1][aRow]=a0.y;
            As[nb][aCol+2][aRow]=a0.z; As[nb][aCol+3][aRow]=a0.w;
            As[nb][aCol+4][aRow]=a1.x; As[nb][aCol+5][aRow]=a1.y;
            As[nb][aCol+6][aRow]=a1.z; As[nb][aCol+7][aRow]=a1.w;
            *reinterpret_cast<float4*>(&Bs[nb][bRow][bCol])   = b0;
            *reinterpret_cast<float4*>(&Bs[nb][bRow][bCol+4]) = b1;
        }
        __syncthreads();
        buf ^= 1;
    }

    // epilogue: acc[i][j] -> C[row0 + ty + 16i][col0 + tx + 16j]
#pragma unroll
    for (int i = 0; i < 8; i++) {
        int r = row0 + ty + 16 * i;
        if (r < M) {
#pragma unroll
            for (int j = 0; j < 8; j++) {
                int c = col0 + tx + 16 * j;
                C[(size_t)r * NC + c] = acc[i][j] + bias[c];
            }
        }
    }
}

// Fused Q/K/V projection: blockIdx.x -> {matrix, column block}
__global__ __launch_bounds__(256) void qkv_sgemm(
    const float* __restrict__ A,
    const float* __restrict__ Wq, const float* __restrict__ Wk,
    const float* __restrict__ Wv,
    const float* __restrict__ bq, const float* __restrict__ bk,
    const float* __restrict__ bv)
{
    const int mat  = blockIdx.x >> 2;
    const int col0 = (blockIdx.x & 3) * 128;
    const float* B; const float* bias; float* C;
    if (mat == 0)      { B = Wq; bias = bq; C = g_qs; }
    else if (mat == 1) { B = Wk; bias = bk; C = g_ks; }
    else               { B = Wv; bias = bv; C = g_vs; }
    sgemm128(A, B, bias, C, col0, Nn);
}

__global__ __launch_bounds__(256) void outs_gemm(const float* __restrict__ W,
                                                 const float* __restrict__ bias)
{
    sgemm128(g_accs, W, bias, g_outs, blockIdx.x * 128, Nn);
}

// -------- vector GEMM: C[n,w,i] = sum_v A[n,v,i]*W[v,w] (+bias[w]) (+resid) ----
__device__ __forceinline__ void vgemm_body(const float* __restrict__ A,
                                           const float* __restrict__ W,
                                           const float* __restrict__ bias,
                                           const float* __restrict__ resid,
                                           float* __restrict__ C)
{
    __shared__ float Ws[32][64];
    __shared__ float Vs[16][96];
    const int tid = threadIdx.x;
    const int n0 = blockIdx.y * 16;
    const int w0 = blockIdx.x * 64;
    const int wi = tid & 31;
    const int ni = tid >> 5;

    float acc[2][2][3];
#pragma unroll
    for (int a = 0; a < 2; a++)
#pragma unroll
        for (int b = 0; b < 2; b++)
#pragma unroll
            for (int c = 0; c < 3; c++) acc[a][b][c] = 0.f;

    for (int k0 = 0; k0 < 128; k0 += 32) {
#pragma unroll
        for (int t = 0; t < 2; t++) {
            int idx = tid * 8 + t * 4;
            int r = idx >> 6;
            int c = idx & 63;
            *reinterpret_cast<float4*>(&Ws[r][c]) =
                *reinterpret_cast<const float4*>(&W[(size_t)(k0 + r) * 128 + w0 + c]);
        }
#pragma unroll
        for (int t = 0; t < 6; t++) {
            int idx = tid + t * 256;
            int nd = idx / 96;
            int off = idx - nd * 96;
            Vs[nd][off] = A[(size_t)(n0 + nd) * 384 + k0 * 3 + off];
        }
        __syncthreads();
#pragma unroll
        for (int k = 0; k < 32; k++) {
            float b0 = Ws[k][wi * 2 + 0];
            float b1 = Ws[k][wi * 2 + 1];
#pragma unroll
            for (int nn = 0; nn < 2; nn++) {
#pragma unroll
                for (int ii = 0; ii < 3; ii++) {
                    float a = Vs[ni * 2 + nn][k * 3 + ii];
                    acc[nn][0][ii] += a * b0;
                    acc[nn][1][ii] += a * b1;
                }
            }
        }
        __syncthreads();
    }
#pragma unroll
    for (int nn = 0; nn < 2; nn++) {
        int n = n0 + ni * 2 + nn;
#pragma unroll
        for (int ww = 0; ww < 2; ww++) {
            int w = w0 + wi * 2 + ww;
            float bvv = bias ? bias[w] : 0.f;
#pragma unroll
            for (int ii = 0; ii < 3; ii++) {
                size_t o = (size_t)n * 384 + (size_t)w * 3 + ii;
                float v = acc[nn][ww][ii] + bvv;
                if (resid) v += resid[o];
                C[o] = v;
            }
        }
    }
}

__global__ void vqkv_gemm(const float* __restrict__ vecs,
                          const float* __restrict__ Wq, const float* __restrict__ Wk,
                          const float* __restrict__ Wv)
{
    const float* W; float* C;
    if (blockIdx.z == 0)      { W = Wq; C = g_qv; }
    else if (blockIdx.z == 1) { W = Wk; C = g_kv; }
    else                      { W = Wv; C = g_vv; }
    vgemm_body(vecs, W, nullptr, nullptr, C);
}

__global__ void vout_gemm(const float* __restrict__ W, const float* __restrict__ bias,
                          const float* __restrict__ vecs, float* __restrict__ out)
{
    vgemm_body(g_accv, W, bias, vecs, out);
}

// ---------------- CSR build ----------------
__global__ void zero_csr()
{
    int i = blockIdx.x * blockDim.x + threadIdx.x;
    if (i < Nn) { g_cnt[i] = 0; g_pos[i] = 0; }
}

__global__ void count_rows()
{
    int e = blockIdx.x * blockDim.x + threadIdx.x;
    if (e < Ee) atomicAdd(&g_cnt[g_idx[e]], 1);
}

__global__ void scan_kernel()
{
    __shared__ int warp_tot[32];
    __shared__ int carry_s;
    const int tid = threadIdx.x;
    const int lane = tid & 31, w = tid >> 5;
    if (tid == 0) { carry_s = 0; g_off[0] = 0; }
    __syncthreads();
    for (int base = 0; base < Nn; base += 1024) {
        int v = (base + tid < Nn) ? g_cnt[base + tid] : 0;
        int x = v;
#pragma unroll
        for (int o = 1; o < 32; o <<= 1) {
            int y = __shfl_up_sync(0xffffffffu, x, o);
            if (lane >= o) x += y;
        }
        if (lane == 31) warp_tot[w] = x;
        __syncthreads();
        if (w == 0) {
            int t = warp_tot[lane];
            int inc = t;
#pragma unroll
            for (int o = 1; o < 32; o <<= 1) {
                int y = __shfl_up_sync(0xffffffffu, inc, o);
                if (lane >= o) inc += y;
            }
            warp_tot[lane] = inc - t;
        }
        __syncthreads();
        int incl = x + warp_tot[w] + carry_s;
        if (base + tid < Nn) g_off[base + tid + 1] = incl;
        __syncthreads();
        if (tid == 1023) carry_s = incl;
        __syncthreads();
    }
}

__global__ void scatter_kernel()
{
    int e = blockIdx.x * blockDim.x + threadIdx.x;
    if (e < Ee) {
        int r = g_idx[e];
        int p = atomicAdd(&g_pos[r], 1);
        g_perm[g_off[r] + p] = e;
    }
}

// ---------------- per-edge logits: one warp per edge ----------------
__global__ __launch_bounds__(256) void edge_logits(
    const float* __restrict__ edge_vec,
    const float* __restrict__ W_edge,
    const float* __restrict__ b_edge)
{
    const int gwarp = (blockIdx.x * 256 + threadIdx.x) >> 5;
    const int lane  = threadIdx.x & 31;
    const int wid   = threadIdx.x >> 5;
    if (gwarp >= Ee) return;
    const int e   = gwarp;
    const int row = g_idx[e];
    const int col = g_idx[Ee + e];

    __shared__ float sh_s[8][8];

    const float4* qp = reinterpret_cast<const float4*>(&g_qs[(size_t)row * Sdim]);
    const float4* kp = reinterpret_cast<const float4*>(&g_ks[(size_t)col * Sdim]);
    float hacc[4];
#pragma unroll
    for (int w = 0; w < 4; w++) {
        float4 q = qp[lane + 32 * w];
        float4 k = kp[lane + 32 * w];
        hacc[w] = q.x * k.x + q.y * k.y + q.z * k.z + q.w * k.w;
    }
    const float4* qv = reinterpret_cast<const float4*>(&g_qv[(size_t)row * 384]);
    const float4* kv = reinterpret_cast<const float4*>(&g_kv[(size_t)col * 384]);
    float pv = 0.f;
#pragma unroll
    for (int w = 0; w < 3; w++) {
        float4 q = qv[lane + 32 * w];
        float4 k = kv[lane + 32 * w];
        pv += q.x * k.x + q.y * k.y + q.z * k.z + q.w * k.w;
    }
#pragma unroll
    for (int o = 16; o; o >>= 1) pv += __shfl_xor_sync(0xffffffffu, pv, o);

#pragma unroll
    for (int w = 0; w < 4; w++)
#pragma unroll
        for (int o = 8; o; o >>= 1)
            hacc[w] += __shfl_down_sync(0xffffffffu, hacc[w], o);
    if (lane == 0) {
#pragma unroll
        for (int w = 0; w < 4; w++) sh_s[wid][2 * w] = hacc[w];
    }
    if (lane == 16) {
#pragma unroll
        for (int w = 0; w < 4; w++) sh_s[wid][2 * w + 1] = hacc[w];
    }

    float ex = edge_vec[(size_t)e * 3 + 0];
    float ey = edge_vec[(size_t)e * 3 + 1];
    float ez = edge_vec[(size_t)e * 3 + 2];
    float d  = sqrtf(ex * ex + ey * ey + ez * ez);
    float cut = (d < 10.f) ? 0.5f * (cosf(PI_F * d * 0.1f) + 1.f) : 0.f;
    float cs = cut / fmaxf(d, 1e-8f);
    float sr = sinf((float)(lane + 1) * (PI_F * 0.1f) * d) * cs;

    float t[8];
    const float* wr = &W_edge[lane * Hh];
#pragma unroll
    for (int h = 0; h < 8; h++) t[h] = sr * wr[h];
#pragma unroll
    for (int o = 16; o; o >>= 1)
#pragma unroll
        for (int h = 0; h < 8; h++)
            t[h] += __shfl_xor_sync(0xffffffffu, t[h], o);

    __syncwarp();
    if (lane == 0) {
        float av = pv * 0.5773502691896258f;
#pragma unroll
        for (int h = 0; h < 8; h++) {
            float logit = (sh_s[wid][h] + av + t[h] + b_edge[h]) * 0.125f;
            g_logits[(size_t)e * 8 + h] = logit;
        }
    }
}

// ---------------- per-node softmax + aggregation (256 threads, MLP 4) ----------
__global__ __launch_bounds__(256) void node_aggregate()
{
    const int n = blockIdx.x;
    const int tid = threadIdx.x;   // 256
    const int beg = g_off[n], end = g_off[n + 1];
    const int deg = end - beg;

    __shared__ unsigned m_u[8];
    __shared__ float m[8], ssum[8];
    constexpr int CH = 64;
    __shared__ float sh_attn[CH][8];
    __shared__ float sh_av[CH];
    __shared__ int   sh_col[CH];

    float acc_s0 = 0.f, acc_s1 = 0.f;
    float acc_v0 = 0.f, acc_v1 = 0.f;

    if (deg > 0) {
        if (tid < 8) { m_u[tid] = 0u; ssum[tid] = 0.f; }
        __syncthreads();
        for (int j = tid; j < deg; j += 256) {
            int e = g_perm[beg + j];
            const float* lp = &g_logits[(size_t)e * 8];
#pragma unroll
            for (int h = 0; h < 8; h++) {
                unsigned u = __float_as_uint(lp[h]);
                u = (u & 0x80000000u) ? ~u : (u | 0x80000000u);
                atomicMax(&m_u[h], u);
            }
        }
        __syncthreads();
        if (tid < 8) {
            unsigned u = m_u[tid];
            u = (u & 0x80000000u) ? (u & 0x7fffffffu) : ~u;
            m[tid] = __uint_as_float(u);
        }
        __syncthreads();
        for (int j = tid; j < deg; j += 256) {
            int e = g_perm[beg + j];
            const float* lp = &g_logits[(size_t)e * 8];
#pragma unroll
            for (int h = 0; h < 8; h++)
                atomicAdd(&ssum[h], expf(lp[h] - m[h]));
        }
        __syncthreads();

        const int h0 = tid >> 6;           // cols [0,256): heads 0..3
        const int h1 = 4 + (tid >> 6);     // cols [256,512): heads 4..7
        for (int c0 = 0; c0 < deg; c0 += CH) {
            int cn = min(CH, deg - c0);
            for (int j = tid; j < cn; j += 256) {
                int e = g_perm[beg + c0 + j];
                sh_col[j] = g_idx[Ee + e];
                const float* lp = &g_logits[(size_t)e * 8];
                float asum = 0.f;
#pragma unroll
                for (int h = 0; h < 8; h++) {
                    float a = expf(lp[h] - m[h]) / (ssum[h] + 1e-9f);
                    sh_attn[j][h] = a;
                    asum += a;
                }
                sh_av[j] = asum * 0.125f;
            }
            __syncthreads();
            for (int j = 0; j < cn; j++) {
                int col = sh_col[j];
                const float* vs = &g_vs[(size_t)col * 512];
                const float* vv = &g_vv[(size_t)col * 384];
                float a0 = sh_attn[j][h0];
                float a1 = sh_attn[j][h1];
                float av = sh_av[j];
                acc_s0 += a0 * vs[tid];
                acc_s1 += a1 * vs[tid + 256];
                acc_v0 += av * vv[tid];
                if (tid < 128) acc_v1 += av * vv[tid + 256];
            }
            __syncthreads();
        }
    }
    g_accs[(size_t)n * 512 + tid]       = acc_s0;
    g_accs[(size_t)n * 512 + tid + 256] = acc_s1;
    g_accv[(size_t)n * 384 + tid]       = acc_v0;
    if (tid < 128) g_accv[(size_t)n * 384 + tid + 256] = acc_v1;
}

// ---------------- residual + layernorm ----------------
__global__ void ln_kernel(const float* __restrict__ scalars,
                          const float* __restrict__ gg, const float* __restrict__ bb,
                          float* __restrict__ out)
{
    const int n = blockIdx.x;
    const int tid = threadIdx.x;  // 512
    float x = scalars[(size_t)n * 512 + tid] + g_outs[(size_t)n * 512 + tid];

    __shared__ float red[16];
    __shared__ float s_mu, s_var;

    float s = x;
#pragma unroll
    for (int o = 16; o; o >>= 1) s += __shfl_down_sync(0xffffffffu, s, o);
    if ((tid & 31) == 0) red[tid >> 5] = s;
    __syncthreads();
    if (tid == 0) {
        float t = 0.f;
#pragma unroll
        for (int i = 0; i < 16; i++) t += red[i];
        s_mu = t * (1.f / 512.f);
    }
    __syncthreads();
    float d = x - s_mu;
    float v = d * d;
#pragma unroll
    for (int o = 16; o; o >>= 1) v += __shfl_down_sync(0xffffffffu, v, o);
    if ((tid & 31) == 0) red[tid >> 5] = v;
    __syncthreads();
    if (tid == 0) {
        float t = 0.f;
#pragma unroll
        for (int i = 0; i < 16; i++) t += red[i];
        s_var = t * (1.f / 512.f);
    }
    __syncthreads();
    out[(size_t)n * 512 + tid] = d * rsqrtf(s_var + 1e-5f) * gg[tid] + bb[tid];
}

// ---------------- launch ----------------
extern "C" void kernel_launch(void* const* d_in, const int* in_sizes, int n_in,
                              void* d_out, int out_size)
{
    const float* scalars  = (const float*)d_in[0];
    const float* vectors  = (const float*)d_in[1];
    const float* edge_vec = (const float*)d_in[2];
    const float* Wq_s = (const float*)d_in[3];
    const float* bq_s = (const float*)d_in[4];
    const float* Wk_s = (const float*)d_in[5];
    const float* bk_s = (const float*)d_in[6];
    const float* Wv_s = (const float*)d_in[7];
    const float* bv_s = (const float*)d_in[8];
    const float* Wq_v = (const float*)d_in[9];
    const float* Wk_v = (const float*)d_in[10];
    const float* Wv_v = (const float*)d_in[11];
    const float* Wout_s = (const float*)d_in[12];
    const float* bout_s = (const float*)d_in[13];
    const float* Wout_v = (const float*)d_in[14];
    const float* bout_v = (const float*)d_in[15];
    const float* W_edge = (const float*)d_in[16];
    const float* b_edge = (const float*)d_in[17];
    const float* ln_g   = (const float*)d_in[18];
    const float* ln_b   = (const float*)d_in[19];
    const int*   eidx_raw = (const int*)d_in[20];

    float* out_s = (float*)d_out;
    float* out_v = (float*)d_out + (size_t)Nn * Sdim;

    // normalize edge indices
    detect_dtype<<<1, 1>>>(eidx_raw);
    convert_idx<<<(2 * Ee + 255) / 256, 256>>>(eidx_raw);

    // CSR build
    zero_csr<<<(Nn + 255) / 256, 256>>>();
    count_rows<<<(Ee + 255) / 256, 256>>>();
    scan_kernel<<<1, 1024>>>();
    scatter_kernel<<<(Ee + 255) / 256, 256>>>();

    // projections
    qkv_sgemm<<<dim3(12, (Nn + 127) / 128), 256>>>(
        scalars, Wq_s, Wk_s, Wv_s, bq_s, bk_s, bv_s);
    vqkv_gemm<<<dim3(Vdim / 64, Nn / 16, 3), 256>>>(vectors, Wq_v, Wk_v, Wv_v);

    // attention
    edge_logits<<<(Ee * 32 + 255) / 256, 256>>>(edge_vec, W_edge, b_edge);
    node_aggregate<<<Nn, 256>>>();

    // outputs
    outs_gemm<<<dim3(4, (Nn + 127) / 128), 256>>>(Wout_s, bout_s);
    vout_gemm<<<dim3(Vdim / 64, Nn / 16), 256>>>(Wout_v, bout_v, vectors, out_v);
    ln_kernel<<<Nn, 512>>>(scalars, ln_g, ln_b, out_s);
}

// round 13
// speedup vs baseline: 1.1493x; 1.0406x over previous
#include <cuda_runtime.h>
#include <cstdint>

#define Nn   10000
#define Ee   160000
#define Sdim 512
#define Vdim 128
#define Hh   8
#define HDim 64
#define Rr   32
#define PI_F 3.14159265358979f

// ---------------- scratch (static device memory; no allocation) ----------------
__device__ float g_qs[Nn * Sdim];
__device__ float g_ks[Nn * Sdim];
__device__ float g_vs[Nn * Sdim];
__device__ float g_qv[Nn * Vdim * 3];
__device__ float g_kv[Nn * Vdim * 3];
__device__ float g_vv[Nn * Vdim * 3];
__device__ float g_logits[Ee * Hh];
__device__ float g_accs[Nn * Sdim];
__device__ float g_accv[Nn * Vdim * 3];
__device__ float g_outs[Nn * Sdim];
__device__ int   g_cnt[Nn];
__device__ int   g_pos[Nn];
__device__ int   g_off[Nn + 1];
__device__ int   g_perm[Ee];
__device__ int   g_idx[2 * Ee];
__device__ int   g_is64;

// ---------------- packed fp32x2 helpers (Blackwell; PTX-only path) -------------
__device__ __forceinline__ uint64_t pack2(float lo, float hi) {
    uint64_t r;
    asm("mov.b64 %0, {%1, %2};" : "=l"(r) : "f"(lo), "f"(hi));
    return r;
}
__device__ __forceinline__ void unpack2(uint64_t v, float& lo, float& hi) {
    asm("mov.b64 {%0, %1}, %2;" : "=f"(lo), "=f"(hi) : "l"(v));
}
__device__ __forceinline__ void ffma2(uint64_t& d, uint64_t a, uint64_t b) {
    asm("fma.rn.f32x2 %0, %1, %2, %0;" : "+l"(d) : "l"(a), "l"(b));
}

// ---------------- edge-index dtype detection + normalization ----------------
__global__ void detect_dtype(const int* __restrict__ raw)
{
    int zeros = 0;
    for (int i = 0; i < 64; i++)
        if (raw[2 * i + 1] == 0) zeros++;
    g_is64 = (zeros >= 60) ? 1 : 0;
}

__global__ void convert_idx(const int* __restrict__ raw)
{
    int e = blockIdx.x * blockDim.x + threadIdx.x;
    if (e < 2 * Ee) {
        int v = g_is64 ? raw[2 * e] : raw[e];
        g_idx[e] = v;
    }
}

// ---------------- SGEMM: C[M,512] tile (128x128) = A @ B + bias ----------------
// Double-buffered, BK=16, 256 threads, 8x8 micro-tile, conflict-free LDS,
// packed fma.rn.f32x2 accumulation (column pairs in 64-bit regs).
__device__ __forceinline__ void sgemm128(const float* __restrict__ A,
                                         const float* __restrict__ B,
                                         const float* __restrict__ bias,
                                         float* __restrict__ C,
                                         int col0, int M)
{
    constexpr int K = 512, NC = 512, BK = 16, NT = K / BK;
    __shared__ float As[2][BK][128];
    __shared__ float Bs[2][BK][128];
    const int tid  = threadIdx.x;
    const int row0 = blockIdx.y * 128;
    const int tx = tid & 15;
    const int ty = tid >> 4;

    const int aRow = tid >> 1;
    const int aCol = (tid & 1) << 3;
    const int bRow = tid >> 4;
    const int bCol = (tid & 15) << 3;

    const bool aValid = (row0 + aRow) < M;
    const float* aPtr = &A[(size_t)(row0 + aRow) * K];
    const float* bPtr = &B[(size_t)bRow * NC + col0 + bCol];

    uint64_t acc2[8][4];
#pragma unroll
    for (int i = 0; i < 8; i++)
#pragma unroll
        for (int p = 0; p < 4; p++) acc2[i][p] = pack2(0.f, 0.f);

    // prologue: tile 0 -> buffer 0
    {
        float4 a0 = make_float4(0.f,0.f,0.f,0.f), a1 = a0;
        if (aValid) {
            a0 = *reinterpret_cast<const float4*>(&aPtr[aCol]);
            a1 = *reinterpret_cast<const float4*>(&aPtr[aCol + 4]);
        }
        float4 b0 = *reinterpret_cast<const float4*>(&bPtr[0]);
        float4 b1 = *reinterpret_cast<const float4*>(&bPtr[4]);
        As[0][aCol+0][aRow]=a0.x; As[0][aCol+1][aRow]=a0.y;
        As[0][aCol+2][aRow]=a0.z; As[0][aCol+3][aRow]=a0.w;
        As[0][aCol+4][aRow]=a1.x; As[0][aCol+5][aRow]=a1.y;
        As[0][aCol+6][aRow]=a1.z; As[0][aCol+7][aRow]=a1.w;
        *reinterpret_cast<float4*>(&Bs[0][bRow][bCol])   = b0;
        *reinterpret_cast<float4*>(&Bs[0][bRow][bCol+4]) = b1;
    }
    __syncthreads();

    int buf = 0;
#pragma unroll 1
    for (int kt = 0; kt < NT; kt++) {
        float4 a0, a1, b0, b1;
        const bool more = (kt + 1) < NT;
        if (more) {
            int k0 = (kt + 1) * BK;
            a0 = make_float4(0.f,0.f,0.f,0.f); a1 = a0;
            if (aValid) {
                a0 = *reinterpret_cast<const float4*>(&aPtr[k0 + aCol]);
                a1 = *reinterpret_cast<const float4*>(&aPtr[k0 + aCol + 4]);
            }
            b0 = *reinterpret_cast<const float4*>(&bPtr[(size_t)k0 * NC]);
            b1 = *reinterpret_cast<const float4*>(&bPtr[(size_t)k0 * NC + 4]);
        }
#pragma unroll
        for (int k = 0; k < BK; k++) {
            float ar[8], br[8];
#pragma unroll
            for (int i = 0; i < 8; i++) ar[i] = As[buf][k][ty + 16 * i];
#pragma unroll
            for (int j = 0; j < 8; j++) br[j] = Bs[buf][k][tx + 16 * j];
            uint64_t ar2[8], br2[4];
#pragma unroll
            for (int i = 0; i < 8; i++) ar2[i] = pack2(ar[i], ar[i]);
#pragma unroll
            for (int p = 0; p < 4; p++) br2[p] = pack2(br[2 * p], br[2 * p + 1]);
#pragma unroll
            for (int i = 0; i < 8; i++)
#pragma unroll
                for (int p = 0; p < 4; p++) ffma2(acc2[i][p], ar2[i], br2[p]);
        }
        if (more) {
            int nb = buf ^ 1;
            As[nb][aCol+0][aRow]=a0.x; As[nb][aCol+1][aRow]=a0.y;
            As[nb][aCol+2][aRow]=a0.z; As[nb][aCol+3][aRow]=a0.w;
            As[nb][aCol+4][aRow]=a1.x; As[nb][aCol+5][aRow]=a1.y;
            As[nb][aCol+6][aRow]=a1.z; As[nb][aCol+7][aRow]=a1.w;
            *reinterpret_cast<float4*>(&Bs[nb][bRow][bCol])   = b0;
            *reinterpret_cast<float4*>(&Bs[nb][bRow][bCol+4]) = b1;
        }
        __syncthreads();
        buf ^= 1;
    }

    // epilogue: acc2[i][p] -> cols (tx+32p, tx+32p+16), row ty+16i
#pragma unroll
    for (int i = 0; i < 8; i++) {
        int r = row0 + ty + 16 * i;
        if (r < M) {
#pragma unroll
            for (int p = 0; p < 4; p++) {
                float lo, hi;
                unpack2(acc2[i][p], lo, hi);
                int c0 = col0 + tx + 32 * p;
                int c1 = c0 + 16;
                C[(size_t)r * NC + c0] = lo + bias[c0];
                C[(size_t)r * NC + c1] = hi + bias[c1];
            }
        }
    }
}

// Fused Q/K/V projection: blockIdx.x -> {matrix, column block}
__global__ __launch_bounds__(256) void qkv_sgemm(
    const float* __restrict__ A,
    const float* __restrict__ Wq, const float* __restrict__ Wk,
    const float* __restrict__ Wv,
    const float* __restrict__ bq, const float* __restrict__ bk,
    const float* __restrict__ bv)
{
    const int mat  = blockIdx.x >> 2;
    const int col0 = (blockIdx.x & 3) * 128;
    const float* B; const float* bias; float* C;
    if (mat == 0)      { B = Wq; bias = bq; C = g_qs; }
    else if (mat == 1) { B = Wk; bias = bk; C = g_ks; }
    else               { B = Wv; bias = bv; C = g_vs; }
    sgemm128(A, B, bias, C, col0, Nn);
}

__global__ __launch_bounds__(256) void outs_gemm(const float* __restrict__ W,
                                                 const float* __restrict__ bias)
{
    sgemm128(g_accs, W, bias, g_outs, blockIdx.x * 128, Nn);
}

// -------- vector GEMM: C[n,w,i] = sum_v A[n,v,i]*W[v,w] (+bias[w]) (+resid) ----
__device__ __forceinline__ void vgemm_body(const float* __restrict__ A,
                                           const float* __restrict__ W,
                                           const float* __restrict__ bias,
                                           const float* __restrict__ resid,
                                           float* __restrict__ C)
{
    __shared__ float Ws[32][64];
    __shared__ float Vs[16][96];
    const int tid = threadIdx.x;
    const int n0 = blockIdx.y * 16;
    const int w0 = blockIdx.x * 64;
    const int wi = tid & 31;
    const int ni = tid >> 5;

    float acc[2][2][3];
#pragma unroll
    for (int a = 0; a < 2; a++)
#pragma unroll
        for (int b = 0; b < 2; b++)
#pragma unroll
            for (int c = 0; c < 3; c++) acc[a][b][c] = 0.f;

    for (int k0 = 0; k0 < 128; k0 += 32) {
#pragma unroll
        for (int t = 0; t < 2; t++) {
            int idx = tid * 8 + t * 4;
            int r = idx >> 6;
            int c = idx & 63;
            *reinterpret_cast<float4*>(&Ws[r][c]) =
                *reinterpret_cast<const float4*>(&W[(size_t)(k0 + r) * 128 + w0 + c]);
        }
#pragma unroll
        for (int t = 0; t < 6; t++) {
            int idx = tid + t * 256;
            int nd = idx / 96;
            int off = idx - nd * 96;
            Vs[nd][off] = A[(size_t)(n0 + nd) * 384 + k0 * 3 + off];
        }
        __syncthreads();
#pragma unroll
        for (int k = 0; k < 32; k++) {
            float b0 = Ws[k][wi * 2 + 0];
            float b1 = Ws[k][wi * 2 + 1];
#pragma unroll
            for (int nn = 0; nn < 2; nn++) {
#pragma unroll
                for (int ii = 0; ii < 3; ii++) {
                    float a = Vs[ni * 2 + nn][k * 3 + ii];
                    acc[nn][0][ii] += a * b0;
                    acc[nn][1][ii] += a * b1;
                }
            }
        }
        __syncthreads();
    }
#pragma unroll
    for (int nn = 0; nn < 2; nn++) {
        int n = n0 + ni * 2 + nn;
#pragma unroll
        for (int ww = 0; ww < 2; ww++) {
            int w = w0 + wi * 2 + ww;
            float bvv = bias ? bias[w] : 0.f;
#pragma unroll
            for (int ii = 0; ii < 3; ii++) {
                size_t o = (size_t)n * 384 + (size_t)w * 3 + ii;
                float v = acc[nn][ww][ii] + bvv;
                if (resid) v += resid[o];
                C[o] = v;
            }
        }
    }
}

__global__ void vqkv_gemm(const float* __restrict__ vecs,
                          const float* __restrict__ Wq, const float* __restrict__ Wk,
                          const float* __restrict__ Wv)
{
    const float* W; float* C;
    if (blockIdx.z == 0)      { W = Wq; C = g_qv; }
    else if (blockIdx.z == 1) { W = Wk; C = g_kv; }
    else                      { W = Wv; C = g_vv; }
    vgemm_body(vecs, W, nullptr, nullptr, C);
}

__global__ void vout_gemm(const float* __restrict__ W, const float* __restrict__ bias,
                          const float* __restrict__ vecs, float* __restrict__ out)
{
    vgemm_body(g_accv, W, bias, vecs, out);
}

// ---------------- CSR build ----------------
__global__ void zero_csr()
{
    int i = blockIdx.x * blockDim.x + threadIdx.x;
    if (i < Nn) { g_cnt[i] = 0; g_pos[i] = 0; }
}

__global__ void count_rows()
{
    int e = blockIdx.x * blockDim.x + threadIdx.x;
    if (e < Ee) atomicAdd(&g_cnt[g_idx[e]], 1);
}

__global__ void scan_kernel()
{
    __shared__ int warp_tot[32];
    __shared__ int carry_s;
    const int tid = threadIdx.x;
    const int lane = tid & 31, w = tid >> 5;
    if (tid == 0) { carry_s = 0; g_off[0] = 0; }
    __syncthreads();
    for (int base = 0; base < Nn; base += 1024) {
        int v = (base + tid < Nn) ? g_cnt[base + tid] : 0;
        int x = v;
#pragma unroll
        for (int o = 1; o < 32; o <<= 1) {
            int y = __shfl_up_sync(0xffffffffu, x, o);
            if (lane >= o) x += y;
        }
        if (lane == 31) warp_tot[w] = x;
        __syncthreads();
        if (w == 0) {
            int t = warp_tot[lane];
            int inc = t;
#pragma unroll
            for (int o = 1; o < 32; o <<= 1) {
                int y = __shfl_up_sync(0xffffffffu, inc, o);
                if (lane >= o) inc += y;
            }
            warp_tot[lane] = inc - t;
        }
        __syncthreads();
        int incl = x + warp_tot[w] + carry_s;
        if (base + tid < Nn) g_off[base + tid + 1] = incl;
        __syncthreads();
        if (tid == 1023) carry_s = incl;
        __syncthreads();
    }
}

__global__ void scatter_kernel()
{
    int e = blockIdx.x * blockDim.x + threadIdx.x;
    if (e < Ee) {
        int r = g_idx[e];
        int p = atomicAdd(&g_pos[r], 1);
        g_perm[g_off[r] + p] = e;
    }
}

// ---------------- per-edge logits: one warp per edge ----------------
__global__ __launch_bounds__(256) void edge_logits(
    const float* __restrict__ edge_vec,
    const float* __restrict__ W_edge,
    const float* __restrict__ b_edge)
{
    const int gwarp = (blockIdx.x * 256 + threadIdx.x) >> 5;
    const int lane  = threadIdx.x & 31;
    const int wid   = threadIdx.x >> 5;
    if (gwarp >= Ee) return;
    const int e   = gwarp;
    const int row = g_idx[e];
    const int col = g_idx[Ee + e];

    __shared__ float sh_s[8][8];

    const float4* qp = reinterpret_cast<const float4*>(&g_qs[(size_t)row * Sdim]);
    const float4* kp = reinterpret_cast<const float4*>(&g_ks[(size_t)col * Sdim]);
    float hacc[4];
#pragma unroll
    for (int w = 0; w < 4; w++) {
        float4 q = qp[lane + 32 * w];
        float4 k = kp[lane + 32 * w];
        hacc[w] = q.x * k.x + q.y * k.y + q.z * k.z + q.w * k.w;
    }
    const float4* qv = reinterpret_cast<const float4*>(&g_qv[(size_t)row * 384]);
    const float4* kv = reinterpret_cast<const float4*>(&g_kv[(size_t)col * 384]);
    float pv = 0.f;
#pragma unroll
    for (int w = 0; w < 3; w++) {
        float4 q = qv[lane + 32 * w];
        float4 k = kv[lane + 32 * w];
        pv += q.x * k.x + q.y * k.y + q.z * k.z + q.w * k.w;
    }
#pragma unroll
    for (int o = 16; o; o >>= 1) pv += __shfl_xor_sync(0xffffffffu, pv, o);

#pragma unroll
    for (int w = 0; w < 4; w++)
#pragma unroll
        for (int o = 8; o; o >>= 1)
            hacc[w] += __shfl_down_sync(0xffffffffu, hacc[w], o);
    if (lane == 0) {
#pragma unroll
        for (int w = 0; w < 4; w++) sh_s[wid][2 * w] = hacc[w];
    }
    if (lane == 16) {
#pragma unroll
        for (int w = 0; w < 4; w++) sh_s[wid][2 * w + 1] = hacc[w];
    }

    float ex = edge_vec[(size_t)e * 3 + 0];
    float ey = edge_vec[(size_t)e * 3 + 1];
    float ez = edge_vec[(size_t)e * 3 + 2];
    float d  = sqrtf(ex * ex + ey * ey + ez * ez);
    float cut = (d < 10.f) ? 0.5f * (cosf(PI_F * d * 0.1f) + 1.f) : 0.f;
    float cs = cut / fmaxf(d, 1e-8f);
    float sr = sinf((float)(lane + 1) * (PI_F * 0.1f) * d) * cs;

    float t[8];
    const float* wr = &W_edge[lane * Hh];
#pragma unroll
    for (int h = 0; h < 8; h++) t[h] = sr * wr[h];
#pragma unroll
    for (int o = 16; o; o >>= 1)
#pragma unroll
        for (int h = 0; h < 8; h++)
            t[h] += __shfl_xor_sync(0xffffffffu, t[h], o);

    __syncwarp();
    if (lane == 0) {
        float av = pv * 0.5773502691896258f;
#pragma unroll
        for (int h = 0; h < 8; h++) {
            float logit = (sh_s[wid][h] + av + t[h] + b_edge[h]) * 0.125f;
            g_logits[(size_t)e * 8 + h] = logit;
        }
    }
}

// ---------------- per-node softmax + aggregation (256 threads, MLP 4) ----------
__global__ __launch_bounds__(256) void node_aggregate()
{
    const int n = blockIdx.x;
    const int tid = threadIdx.x;   // 256
    const int beg = g_off[n], end = g_off[n + 1];
    const int deg = end - beg;

    __shared__ unsigned m_u[8];
    __shared__ float m[8], ssum[8];
    constexpr int CH = 64;
    __shared__ float sh_attn[CH][8];
    __shared__ float sh_av[CH];
    __shared__ int   sh_col[CH];

    float acc_s0 = 0.f, acc_s1 = 0.f;
    float acc_v0 = 0.f, acc_v1 = 0.f;

    if (deg > 0) {
        if (tid < 8) { m_u[tid] = 0u; ssum[tid] = 0.f; }
        __syncthreads();
        for (int j = tid; j < deg; j += 256) {
            int e = g_perm[beg + j];
            const float* lp = &g_logits[(size_t)e * 8];
#pragma unroll
            for (int h = 0; h < 8; h++) {
                unsigned u = __float_as_uint(lp[h]);
                u = (u & 0x80000000u) ? ~u : (u | 0x80000000u);
                atomicMax(&m_u[h], u);
            }
        }
        __syncthreads();
        if (tid < 8) {
            unsigned u = m_u[tid];
            u = (u & 0x80000000u) ? (u & 0x7fffffffu) : ~u;
            m[tid] = __uint_as_float(u);
        }
        __syncthreads();
        for (int j = tid; j < deg; j += 256) {
            int e = g_perm[beg + j];
            const float* lp = &g_logits[(size_t)e * 8];
#pragma unroll
            for (int h = 0; h < 8; h++)
                atomicAdd(&ssum[h], expf(lp[h] - m[h]));
        }
        __syncthreads();

        const int h0 = tid >> 6;           // cols [0,256): heads 0..3
        const int h1 = 4 + (tid >> 6);     // cols [256,512): heads 4..7
        for (int c0 = 0; c0 < deg; c0 += CH) {
            int cn = min(CH, deg - c0);
            for (int j = tid; j < cn; j += 256) {
                int e = g_perm[beg + c0 + j];
                sh_col[j] = g_idx[Ee + e];
                const float* lp = &g_logits[(size_t)e * 8];
                float asum = 0.f;
#pragma unroll
                for (int h = 0; h < 8; h++) {
                    float a = expf(lp[h] - m[h]) / (ssum[h] + 1e-9f);
                    sh_attn[j][h] = a;
                    asum += a;
                }
                sh_av[j] = asum * 0.125f;
            }
            __syncthreads();
            for (int j = 0; j < cn; j++) {
                int col = sh_col[j];
                const float* vs = &g_vs[(size_t)col * 512];
                const float* vv = &g_vv[(size_t)col * 384];
                float a0 = sh_attn[j][h0];
                float a1 = sh_attn[j][h1];
                float av = sh_av[j];
                acc_s0 += a0 * vs[tid];
                acc_s1 += a1 * vs[tid + 256];
                acc_v0 += av * vv[tid];
                if (tid < 128) acc_v1 += av * vv[tid + 256];
            }
            __syncthreads();
        }
    }
    g_accs[(size_t)n * 512 + tid]       = acc_s0;
    g_accs[(size_t)n * 512 + tid + 256] = acc_s1;
    g_accv[(size_t)n * 384 + tid]       = acc_v0;
    if (tid < 128) g_accv[(size_t)n * 384 + tid + 256] = acc_v1;
}

// ---------------- residual + layernorm ----------------
__global__ void ln_kernel(const float* __restrict__ scalars,
                          const float* __restrict__ gg, const float* __restrict__ bb,
                          float* __restrict__ out)
{
    const int n = blockIdx.x;
    const int tid = threadIdx.x;  // 512
    float x = scalars[(size_t)n * 512 + tid] + g_outs[(size_t)n * 512 + tid];

    __shared__ float red[16];
    __shared__ float s_mu, s_var;

    float s = x;
#pragma unroll
    for (int o = 16; o; o >>= 1) s += __shfl_down_sync(0xffffffffu, s, o);
    if ((tid & 31) == 0) red[tid >> 5] = s;
    __syncthreads();
    if (tid == 0) {
        float t = 0.f;
#pragma unroll
        for (int i = 0; i < 16; i++) t += red[i];
        s_mu = t * (1.f / 512.f);
    }
    __syncthreads();
    float d = x - s_mu;
    float v = d * d;
#pragma unroll
    for (int o = 16; o; o >>= 1) v += __shfl_down_sync(0xffffffffu, v, o);
    if ((tid & 31) == 0) red[tid >> 5] = v;
    __syncthreads();
    if (tid == 0) {
        float t = 0.f;
#pragma unroll
        for (int i = 0; i < 16; i++) t += red[i];
        s_var = t * (1.f / 512.f);
    }
    __syncthreads();
    out[(size_t)n * 512 + tid] = d * rsqrtf(s_var + 1e-5f) * gg[tid] + bb[tid];
}

// ---------------- launch ----------------
extern "C" void kernel_launch(void* const* d_in, const int* in_sizes, int n_in,
                              void* d_out, int out_size)
{
    const float* scalars  = (const float*)d_in[0];
    const float* vectors  = (const float*)d_in[1];
    const float* edge_vec = (const float*)d_in[2];
    const float* Wq_s = (const float*)d_in[3];
    const float* bq_s = (const float*)d_in[4];
    const float* Wk_s = (const float*)d_in[5];
    const float* bk_s = (const float*)d_in[6];
    const float* Wv_s = (const float*)d_in[7];
    const float* bv_s = (const float*)d_in[8];
    const float* Wq_v = (const float*)d_in[9];
    const float* Wk_v = (const float*)d_in[10];
    const float* Wv_v = (const float*)d_in[11];
    const float* Wout_s = (const float*)d_in[12];
    const float* bout_s = (const float*)d_in[13];
    const float* Wout_v = (const float*)d_in[14];
    const float* bout_v = (const float*)d_in[15];
    const float* W_edge = (const float*)d_in[16];
    const float* b_edge = (const float*)d_in[17];
    const float* ln_g   = (const float*)d_in[18];
    const float* ln_b   = (const float*)d_in[19];
    const int*   eidx_raw = (const int*)d_in[20];

    float* out_s = (float*)d_out;
    float* out_v = (float*)d_out + (size_t)Nn * Sdim;

    // normalize edge indices
    detect_dtype<<<1, 1>>>(eidx_raw);
    convert_idx<<<(2 * Ee + 255) / 256, 256>>>(eidx_raw);

    // CSR build
    zero_csr<<<(Nn + 255) / 256, 256>>>();
    count_rows<<<(Ee + 255) / 256, 256>>>();
    scan_kernel<<<1, 1024>>>();
    scatter_kernel<<<(Ee + 255) / 256, 256>>>();

    // projections
    qkv_sgemm<<<dim3(12, (Nn + 127) / 128), 256>>>(
        scalars, Wq_s, Wk_s, Wv_s, bq_s, bk_s, bv_s);
    vqkv_gemm<<<dim3(Vdim / 64, Nn / 16, 3), 256>>>(vectors, Wq_v, Wk_v, Wv_v);

    // attention
    edge_logits<<<(Ee * 32 + 255) / 256, 256>>>(edge_vec, W_edge, b_edge);
    node_aggregate<<<Nn, 256>>>();

    // outputs
    outs_gemm<<<dim3(4, (Nn + 127) / 128), 256>>>(Wout_s, bout_s);
    vout_gemm<<<dim3(Vdim / 64, Nn / 16), 256>>>(Wout_v, bout_v, vectors, out_v);
    ln_kernel<<<Nn, 512>>>(scalars, ln_g, ln_b, out_s);
}

// round 14
// speedup vs baseline: 1.1661x; 1.0146x over previous
#include <cuda_runtime.h>
#include <cstdint>

#define Nn   10000
#define Ee   160000
#define Sdim 512
#define Vdim 128
#define Hh   8
#define HDim 64
#define Rr   32
#define PI_F 3.14159265358979f

// ---------------- scratch (static device memory; no allocation) ----------------
__device__ float g_qs[Nn * Sdim];
__device__ float g_ks[Nn * Sdim];
__device__ float g_vs[Nn * Sdim];
__device__ float g_qv[Nn * Vdim * 3];
__device__ float g_kv[Nn * Vdim * 3];
__device__ float g_vv[Nn * Vdim * 3];
__device__ float g_logits[Ee * Hh];
__device__ float g_accs[Nn * Sdim];
__device__ float g_accv[Nn * Vdim * 3];
__device__ float g_outs[Nn * Sdim];
__device__ int   g_cnt[Nn];
__device__ int   g_pos[Nn];
__device__ int   g_off[Nn + 1];
__device__ int   g_perm[Ee];
__device__ int   g_idx[2 * Ee];
__device__ int   g_is64;

// ---------------- packed fp32x2 helpers (Blackwell; PTX-only path) -------------
__device__ __forceinline__ uint64_t pack2(float lo, float hi) {
    uint64_t r;
    asm("mov.b64 %0, {%1, %2};" : "=l"(r) : "f"(lo), "f"(hi));
    return r;
}
__device__ __forceinline__ void unpack2(uint64_t v, float& lo, float& hi) {
    asm("mov.b64 {%0, %1}, %2;" : "=f"(lo), "=f"(hi) : "l"(v));
}
__device__ __forceinline__ void ffma2(uint64_t& d, uint64_t a, uint64_t b) {
    asm("fma.rn.f32x2 %0, %1, %2, %0;" : "+l"(d) : "l"(a), "l"(b));
}

// ---------------- edge-index dtype detection + normalization ----------------
__global__ void detect_dtype(const int* __restrict__ raw)
{
    int zeros = 0;
    for (int i = 0; i < 64; i++)
        if (raw[2 * i + 1] == 0) zeros++;
    g_is64 = (zeros >= 60) ? 1 : 0;
}

__global__ void convert_idx(const int* __restrict__ raw)
{
    int e = blockIdx.x * blockDim.x + threadIdx.x;
    if (e < 2 * Ee) {
        int v = g_is64 ? raw[2 * e] : raw[e];
        g_idx[e] = v;
    }
}

// ---------------- SGEMM: C[M,512] tile (128x128) = A @ B + bias ----------------
// Double-buffered, BK=16, 256 threads, 8x8 micro-tile.
// Columns handled as adjacent pairs (c = 2*tx + 32*p): B operand pair comes
// straight from one LDS.64 into the fma.rn.f32x2 source; epilogue is float2.
__device__ __forceinline__ void sgemm128(const float* __restrict__ A,
                                         const float* __restrict__ B,
                                         const float* __restrict__ bias,
                                         float* __restrict__ C,
                                         int col0, int M)
{
    constexpr int K = 512, NC = 512, BK = 16, NT = K / BK;
    __shared__ float As[2][BK][128];
    __shared__ float Bs[2][BK][128];
    const int tid  = threadIdx.x;
    const int row0 = blockIdx.y * 128;
    const int tx = tid & 15;
    const int ty = tid >> 4;

    const int aRow = tid >> 1;
    const int aCol = (tid & 1) << 3;
    const int bRow = tid >> 4;
    const int bCol = (tid & 15) << 3;

    const bool aValid = (row0 + aRow) < M;
    const float* aPtr = &A[(size_t)(row0 + aRow) * K];
    const float* bPtr = &B[(size_t)bRow * NC + col0 + bCol];

    uint64_t acc2[8][4];
#pragma unroll
    for (int i = 0; i < 8; i++)
#pragma unroll
        for (int p = 0; p < 4; p++) acc2[i][p] = pack2(0.f, 0.f);

    // prologue: tile 0 -> buffer 0
    {
        float4 a0 = make_float4(0.f,0.f,0.f,0.f), a1 = a0;
        if (aValid) {
            a0 = *reinterpret_cast<const float4*>(&aPtr[aCol]);
            a1 = *reinterpret_cast<const float4*>(&aPtr[aCol + 4]);
        }
        float4 b0 = *reinterpret_cast<const float4*>(&bPtr[0]);
        float4 b1 = *reinterpret_cast<const float4*>(&bPtr[4]);
        As[0][aCol+0][aRow]=a0.x; As[0][aCol+1][aRow]=a0.y;
        As[0][aCol+2][aRow]=a0.z; As[0][aCol+3][aRow]=a0.w;
        As[0][aCol+4][aRow]=a1.x; As[0][aCol+5][aRow]=a1.y;
        As[0][aCol+6][aRow]=a1.z; As[0][aCol+7][aRow]=a1.w;
        *reinterpret_cast<float4*>(&Bs[0][bRow][bCol])   = b0;
        *reinterpret_cast<float4*>(&Bs[0][bRow][bCol+4]) = b1;
    }
    __syncthreads();

    int buf = 0;
#pragma unroll 1
    for (int kt = 0; kt < NT; kt++) {
        float4 a0, a1, b0, b1;
        const bool more = (kt + 1) < NT;
        if (more) {
            int k0 = (kt + 1) * BK;
            a0 = make_float4(0.f,0.f,0.f,0.f); a1 = a0;
            if (aValid) {
                a0 = *reinterpret_cast<const float4*>(&aPtr[k0 + aCol]);
                a1 = *reinterpret_cast<const float4*>(&aPtr[k0 + aCol + 4]);
            }
            b0 = *reinterpret_cast<const float4*>(&bPtr[(size_t)k0 * NC]);
            b1 = *reinterpret_cast<const float4*>(&bPtr[(size_t)k0 * NC + 4]);
        }
#pragma unroll
        for (int k = 0; k < BK; k++) {
            uint64_t ar2[8], br2[4];
#pragma unroll
            for (int i = 0; i < 8; i++) {
                float a = As[buf][k][ty + 16 * i];
                ar2[i] = pack2(a, a);
            }
#pragma unroll
            for (int p = 0; p < 4; p++)
                br2[p] = *reinterpret_cast<const uint64_t*>(&Bs[buf][k][2 * tx + 32 * p]);
#pragma unroll
            for (int i = 0; i < 8; i++)
#pragma unroll
                for (int p = 0; p < 4; p++) ffma2(acc2[i][p], ar2[i], br2[p]);
        }
        if (more) {
            int nb = buf ^ 1;
            As[nb][aCol+0][aRow]=a0.x; As[nb][aCol+1][aRow]=a0.y;
            As[nb][aCol+2][aRow]=a0.z; As[nb][aCol+3][aRow]=a0.w;
            As[nb][aCol+4][aRow]=a1.x; As[nb][aCol+5][aRow]=a1.y;
            As[nb][aCol+6][aRow]=a1.z; As[nb][aCol+7][aRow]=a1.w;
            *reinterpret_cast<float4*>(&Bs[nb][bRow][bCol])   = b0;
            *reinterpret_cast<float4*>(&Bs[nb][bRow][bCol+4]) = b1;
        }
        __syncthreads();
        buf ^= 1;
    }

    // epilogue: acc2[i][p] -> row ty+16i, cols (2tx+32p, 2tx+32p+1)
#pragma unroll
    for (int i = 0; i < 8; i++) {
        int r = row0 + ty + 16 * i;
        if (r < M) {
#pragma unroll
            for (int p = 0; p < 4; p++) {
                float lo, hi;
                unpack2(acc2[i][p], lo, hi);
                int c = col0 + 2 * tx + 32 * p;
                float2 bv = *reinterpret_cast<const float2*>(&bias[c]);
                float2 o = make_float2(lo + bv.x, hi + bv.y);
                *reinterpret_cast<float2*>(&C[(size_t)r * NC + c]) = o;
            }
        }
    }
}

// Fused Q/K/V projection: blockIdx.x -> {matrix, column block}
__global__ __launch_bounds__(256) void qkv_sgemm(
    const float* __restrict__ A,
    const float* __restrict__ Wq, const float* __restrict__ Wk,
    const float* __restrict__ Wv,
    const float* __restrict__ bq, const float* __restrict__ bk,
    const float* __restrict__ bv)
{
    const int mat  = blockIdx.x >> 2;
    const int col0 = (blockIdx.x & 3) * 128;
    const float* B; const float* bias; float* C;
    if (mat == 0)      { B = Wq; bias = bq; C = g_qs; }
    else if (mat == 1) { B = Wk; bias = bk; C = g_ks; }
    else               { B = Wv; bias = bv; C = g_vs; }
    sgemm128(A, B, bias, C, col0, Nn);
}

__global__ __launch_bounds__(256) void outs_gemm(const float* __restrict__ W,
                                                 const float* __restrict__ bias)
{
    sgemm128(g_accs, W, bias, g_outs, blockIdx.x * 128, Nn);
}

// -------- vector GEMM: C[n,w,i] = sum_v A[n,v,i]*W[v,w] (+bias[w]) (+resid) ----
__device__ __forceinline__ void vgemm_body(const float* __restrict__ A,
                                           const float* __restrict__ W,
                                           const float* __restrict__ bias,
                                           const float* __restrict__ resid,
                                           float* __restrict__ C)
{
    __shared__ float Ws[32][64];
    __shared__ float Vs[16][96];
    const int tid = threadIdx.x;
    const int n0 = blockIdx.y * 16;
    const int w0 = blockIdx.x * 64;
    const int wi = tid & 31;
    const int ni = tid >> 5;

    float acc[2][2][3];
#pragma unroll
    for (int a = 0; a < 2; a++)
#pragma unroll
        for (int b = 0; b < 2; b++)
#pragma unroll
            for (int c = 0; c < 3; c++) acc[a][b][c] = 0.f;

    for (int k0 = 0; k0 < 128; k0 += 32) {
#pragma unroll
        for (int t = 0; t < 2; t++) {
            int idx = tid * 8 + t * 4;
            int r = idx >> 6;
            int c = idx & 63;
            *reinterpret_cast<float4*>(&Ws[r][c]) =
                *reinterpret_cast<const float4*>(&W[(size_t)(k0 + r) * 128 + w0 + c]);
        }
#pragma unroll
        for (int t = 0; t < 6; t++) {
            int idx = tid + t * 256;
            int nd = idx / 96;
            int off = idx - nd * 96;
            Vs[nd][off] = A[(size_t)(n0 + nd) * 384 + k0 * 3 + off];
        }
        __syncthreads();
#pragma unroll
        for (int k = 0; k < 32; k++) {
            float b0 = Ws[k][wi * 2 + 0];
            float b1 = Ws[k][wi * 2 + 1];
#pragma unroll
            for (int nn = 0; nn < 2; nn++) {
#pragma unroll
                for (int ii = 0; ii < 3; ii++) {
                    float a = Vs[ni * 2 + nn][k * 3 + ii];
                    acc[nn][0][ii] += a * b0;
                    acc[nn][1][ii] += a * b1;
                }
            }
        }
        __syncthreads();
    }
#pragma unroll
    for (int nn = 0; nn < 2; nn++) {
        int n = n0 + ni * 2 + nn;
#pragma unroll
        for (int ww = 0; ww < 2; ww++) {
            int w = w0 + wi * 2 + ww;
            float bvv = bias ? bias[w] : 0.f;
#pragma unroll
            for (int ii = 0; ii < 3; ii++) {
                size_t o = (size_t)n * 384 + (size_t)w * 3 + ii;
                float v = acc[nn][ww][ii] + bvv;
                if (resid) v += resid[o];
                C[o] = v;
            }
        }
    }
}

__global__ void vqkv_gemm(const float* __restrict__ vecs,
                          const float* __restrict__ Wq, const float* __restrict__ Wk,
                          const float* __restrict__ Wv)
{
    const float* W; float* C;
    if (blockIdx.z == 0)      { W = Wq; C = g_qv; }
    else if (blockIdx.z == 1) { W = Wk; C = g_kv; }
    else                      { W = Wv; C = g_vv; }
    vgemm_body(vecs, W, nullptr, nullptr, C);
}

__global__ void vout_gemm(const float* __restrict__ W, const float* __restrict__ bias,
                          const float* __restrict__ vecs, float* __restrict__ out)
{
    vgemm_body(g_accv, W, bias, vecs, out);
}

// ---------------- CSR build ----------------
__global__ void zero_csr()
{
    int i = blockIdx.x * blockDim.x + threadIdx.x;
    if (i < Nn) { g_cnt[i] = 0; g_pos[i] = 0; }
}

__global__ void count_rows()
{
    int e = blockIdx.x * blockDim.x + threadIdx.x;
    if (e < Ee) atomicAdd(&g_cnt[g_idx[e]], 1);
}

__global__ void scan_kernel()
{
    __shared__ int warp_tot[32];
    __shared__ int carry_s;
    const int tid = threadIdx.x;
    const int lane = tid & 31, w = tid >> 5;
    if (tid == 0) { carry_s = 0; g_off[0] = 0; }
    __syncthreads();
    for (int base = 0; base < Nn; base += 1024) {
        int v = (base + tid < Nn) ? g_cnt[base + tid] : 0;
        int x = v;
#pragma unroll
        for (int o = 1; o < 32; o <<= 1) {
            int y = __shfl_up_sync(0xffffffffu, x, o);
            if (lane >= o) x += y;
        }
        if (lane == 31) warp_tot[w] = x;
        __syncthreads();
        if (w == 0) {
            int t = warp_tot[lane];
            int inc = t;
#pragma unroll
            for (int o = 1; o < 32; o <<= 1) {
                int y = __shfl_up_sync(0xffffffffu, inc, o);
                if (lane >= o) inc += y;
            }
            warp_tot[lane] = inc - t;
        }
        __syncthreads();
        int incl = x + warp_tot[w] + carry_s;
        if (base + tid < Nn) g_off[base + tid + 1] = incl;
        __syncthreads();
        if (tid == 1023) carry_s = incl;
        __syncthreads();
    }
}

__global__ void scatter_kernel()
{
    int e = blockIdx.x * blockDim.x + threadIdx.x;
    if (e < Ee) {
        int r = g_idx[e];
        int p = atomicAdd(&g_pos[r], 1);
        g_perm[g_off[r] + p] = e;
    }
}

// ---------------- per-edge logits: one warp per edge ----------------
__global__ __launch_bounds__(256) void edge_logits(
    const float* __restrict__ edge_vec,
    const float* __restrict__ W_edge,
    const float* __restrict__ b_edge)
{
    const int gwarp = (blockIdx.x * 256 + threadIdx.x) >> 5;
    const int lane  = threadIdx.x & 31;
    const int wid   = threadIdx.x >> 5;
    if (gwarp >= Ee) return;
    const int e   = gwarp;
    const int row = g_idx[e];
    const int col = g_idx[Ee + e];

    __shared__ float sh_s[8][8];

    const float4* qp = reinterpret_cast<const float4*>(&g_qs[(size_t)row * Sdim]);
    const float4* kp = reinterpret_cast<const float4*>(&g_ks[(size_t)col * Sdim]);
    float hacc[4];
#pragma unroll
    for (int w = 0; w < 4; w++) {
        float4 q = qp[lane + 32 * w];
        float4 k = kp[lane + 32 * w];
        hacc[w] = q.x * k.x + q.y * k.y + q.z * k.z + q.w * k.w;
    }
    const float4* qv = reinterpret_cast<const float4*>(&g_qv[(size_t)row * 384]);
    const float4* kv = reinterpret_cast<const float4*>(&g_kv[(size_t)col * 384]);
    float pv = 0.f;
#pragma unroll
    for (int w = 0; w < 3; w++) {
        float4 q = qv[lane + 32 * w];
        float4 k = kv[lane + 32 * w];
        pv += q.x * k.x + q.y * k.y + q.z * k.z + q.w * k.w;
    }
#pragma unroll
    for (int o = 16; o; o >>= 1) pv += __shfl_xor_sync(0xffffffffu, pv, o);

#pragma unroll
    for (int w = 0; w < 4; w++)
#pragma unroll
        for (int o = 8; o; o >>= 1)
            hacc[w] += __shfl_down_sync(0xffffffffu, hacc[w], o);
    if (lane == 0) {
#pragma unroll
        for (int w = 0; w < 4; w++) sh_s[wid][2 * w] = hacc[w];
    }
    if (lane == 16) {
#pragma unroll
        for (int w = 0; w < 4; w++) sh_s[wid][2 * w + 1] = hacc[w];
    }

    float ex = edge_vec[(size_t)e * 3 + 0];
    float ey = edge_vec[(size_t)e * 3 + 1];
    float ez = edge_vec[(size_t)e * 3 + 2];
    float d  = sqrtf(ex * ex + ey * ey + ez * ez);
    float cut = (d < 10.f) ? 0.5f * (cosf(PI_F * d * 0.1f) + 1.f) : 0.f;
    float cs = cut / fmaxf(d, 1e-8f);
    float sr = sinf((float)(lane + 1) * (PI_F * 0.1f) * d) * cs;

    float t[8];
    const float* wr = &W_edge[lane * Hh];
#pragma unroll
    for (int h = 0; h < 8; h++) t[h] = sr * wr[h];
#pragma unroll
    for (int o = 16; o; o >>= 1)
#pragma unroll
        for (int h = 0; h < 8; h++)
            t[h] += __shfl_xor_sync(0xffffffffu, t[h], o);

    __syncwarp();
    if (lane == 0) {
        float av = pv * 0.5773502691896258f;
#pragma unroll
        for (int h = 0; h < 8; h++) {
            float logit = (sh_s[wid][h] + av + t[h] + b_edge[h]) * 0.125f;
            g_logits[(size_t)e * 8 + h] = logit;
        }
    }
}

// ---------------- per-node softmax + aggregation (256 threads, MLP 4) ----------
__global__ __launch_bounds__(256) void node_aggregate()
{
    const int n = blockIdx.x;
    const int tid = threadIdx.x;   // 256
    const int beg = g_off[n], end = g_off[n + 1];
    const int deg = end - beg;

    __shared__ unsigned m_u[8];
    __shared__ float m[8], ssum[8];
    constexpr int CH = 64;
    __shared__ float sh_attn[CH][8];
    __shared__ float sh_av[CH];
    __shared__ int   sh_col[CH];

    float acc_s0 = 0.f, acc_s1 = 0.f;
    float acc_v0 = 0.f, acc_v1 = 0.f;

    if (deg > 0) {
        if (tid < 8) { m_u[tid] = 0u; ssum[tid] = 0.f; }
        __syncthreads();
        for (int j = tid; j < deg; j += 256) {
            int e = g_perm[beg + j];
            const float* lp = &g_logits[(size_t)e * 8];
#pragma unroll
            for (int h = 0; h < 8; h++) {
                unsigned u = __float_as_uint(lp[h]);
                u = (u & 0x80000000u) ? ~u : (u | 0x80000000u);
                atomicMax(&m_u[h], u);
            }
        }
        __syncthreads();
        if (tid < 8) {
            unsigned u = m_u[tid];
            u = (u & 0x80000000u) ? (u & 0x7fffffffu) : ~u;
            m[tid] = __uint_as_float(u);
        }
        __syncthreads();
        for (int j = tid; j < deg; j += 256) {
            int e = g_perm[beg + j];
            const float* lp = &g_logits[(size_t)e * 8];
#pragma unroll
            for (int h = 0; h < 8; h++)
                atomicAdd(&ssum[h], expf(lp[h] - m[h]));
        }
        __syncthreads();

        const int h0 = tid >> 6;           // cols [0,256): heads 0..3
        const int h1 = 4 + (tid >> 6);     // cols [256,512): heads 4..7
        for (int c0 = 0; c0 < deg; c0 += CH) {
            int cn = min(CH, deg - c0);
            for (int j = tid; j < cn; j += 256) {
                int e = g_perm[beg + c0 + j];
                sh_col[j] = g_idx[Ee + e];
                const float* lp = &g_logits[(size_t)e * 8];
                float asum = 0.f;
#pragma unroll
                for (int h = 0; h < 8; h++) {
                    float a = expf(lp[h] - m[h]) / (ssum[h] + 1e-9f);
                    sh_attn[j][h] = a;
                    asum += a;
                }
                sh_av[j] = asum * 0.125f;
            }
            __syncthreads();
            for (int j = 0; j < cn; j++) {
                int col = sh_col[j];
                const float* vs = &g_vs[(size_t)col * 512];
                const float* vv = &g_vv[(size_t)col * 384];
                float a0 = sh_attn[j][h0];
                float a1 = sh_attn[j][h1];
                float av = sh_av[j];
                acc_s0 += a0 * vs[tid];
                acc_s1 += a1 * vs[tid + 256];
                acc_v0 += av * vv[tid];
                if (tid < 128) acc_v1 += av * vv[tid + 256];
            }
            __syncthreads();
        }
    }
    g_accs[(size_t)n * 512 + tid]       = acc_s0;
    g_accs[(size_t)n * 512 + tid + 256] = acc_s1;
    g_accv[(size_t)n * 384 + tid]       = acc_v0;
    if (tid < 128) g_accv[(size_t)n * 384 + tid + 256] = acc_v1;
}

// ---------------- residual + layernorm ----------------
__global__ void ln_kernel(const float* __restrict__ scalars,
                          const float* __restrict__ gg, const float* __restrict__ bb,
                          float* __restrict__ out)
{
    const int n = blockIdx.x;
    const int tid = threadIdx.x;  // 512
    float x = scalars[(size_t)n * 512 + tid] + g_outs[(size_t)n * 512 + tid];

    __shared__ float red[16];
    __shared__ float s_mu, s_var;

    float s = x;
#pragma unroll
    for (int o = 16; o; o >>= 1) s += __shfl_down_sync(0xffffffffu, s, o);
    if ((tid & 31) == 0) red[tid >> 5] = s;
    __syncthreads();
    if (tid == 0) {
        float t = 0.f;
#pragma unroll
        for (int i = 0; i < 16; i++) t += red[i];
        s_mu = t * (1.f / 512.f);
    }
    __syncthreads();
    float d = x - s_mu;
    float v = d * d;
#pragma unroll
    for (int o = 16; o; o >>= 1) v += __shfl_down_sync(0xffffffffu, v, o);
    if ((tid & 31) == 0) red[tid >> 5] = v;
    __syncthreads();
    if (tid == 0) {
        float t = 0.f;
#pragma unroll
        for (int i = 0; i < 16; i++) t += red[i];
        s_var = t * (1.f / 512.f);
    }
    __syncthreads();
    out[(size_t)n * 512 + tid] = d * rsqrtf(s_var + 1e-5f) * gg[tid] + bb[tid];
}

// ---------------- launch ----------------
extern "C" void kernel_launch(void* const* d_in, const int* in_sizes, int n_in,
                              void* d_out, int out_size)
{
    const float* scalars  = (const float*)d_in[0];
    const float* vectors  = (const float*)d_in[1];
    const float* edge_vec = (const float*)d_in[2];
    const float* Wq_s = (const float*)d_in[3];
    const float* bq_s = (const float*)d_in[4];
    const float* Wk_s = (const float*)d_in[5];
    const float* bk_s = (const float*)d_in[6];
    const float* Wv_s = (const float*)d_in[7];
    const float* bv_s = (const float*)d_in[8];
    const float* Wq_v = (const float*)d_in[9];
    const float* Wk_v = (const float*)d_in[10];
    const float* Wv_v = (const float*)d_in[11];
    const float* Wout_s = (const float*)d_in[12];
    const float* bout_s = (const float*)d_in[13];
    const float* Wout_v = (const float*)d_in[14];
    const float* bout_v = (const float*)d_in[15];
    const float* W_edge = (const float*)d_in[16];
    const float* b_edge = (const float*)d_in[17];
    const float* ln_g   = (const float*)d_in[18];
    const float* ln_b   = (const float*)d_in[19];
    const int*   eidx_raw = (const int*)d_in[20];

    float* out_s = (float*)d_out;
    float* out_v = (float*)d_out + (size_t)Nn * Sdim;

    // normalize edge indices
    detect_dtype<<<1, 1>>>(eidx_raw);
    convert_idx<<<(2 * Ee + 255) / 256, 256>>>(eidx_raw);

    // CSR build
    zero_csr<<<(Nn + 255) / 256, 256>>>();
    count_rows<<<(Ee + 255) / 256, 256>>>();
    scan_kernel<<<1, 1024>>>();
    scatter_kernel<<<(Ee + 255) / 256, 256>>>();

    // projections
    qkv_sgemm<<<dim3(12, (Nn + 127) / 128), 256>>>(
        scalars, Wq_s, Wk_s, Wv_s, bq_s, bk_s, bv_s);
    vqkv_gemm<<<dim3(Vdim / 64, Nn / 16, 3), 256>>>(vectors, Wq_v, Wk_v, Wv_v);

    // attention
    edge_logits<<<(Ee * 32 + 255) / 256, 256>>>(edge_vec, W_edge, b_edge);
    node_aggregate<<<Nn, 256>>>();

    // outputs
    outs_gemm<<<dim3(4, (Nn + 127) / 128), 256>>>(Wout_s, bout_s);
    vout_gemm<<<dim3(Vdim / 64, Nn / 16), 256>>>(Wout_v, bout_v, vectors, out_v);
    ln_kernel<<<Nn, 512>>>(scalars, ln_g, ln_b, out_s);
}